// round 4
// baseline (speedup 1.0000x reference)
#include <cuda_runtime.h>
#include <stdint.h>

// Problem constants
#define NSAMP 1000000
#define KMIX  64
#define DDIM  16

// Scratch (static __device__ — no allocation)
__device__ int   g_z[NSAMP];
__device__ float g_logits[KMIX];

// ---------------------------------------------------------------------------
// Threefry-2x32, key = (0, 42), PARTITIONABLE counter scheme:
// counter = (hi, lo) = (0, i) for flat element i < 2^32; output = o0 ^ o1.
// Rotation schedule per JAX: 5 groups of 4 rounds, [13,15,26,6]/[17,29,16,24].
// ---------------------------------------------------------------------------
__device__ __forceinline__ void tf_round(uint32_t& x0, uint32_t& x1, int r) {
    x0 += x1;
    x1 = (x1 << r) | (x1 >> (32 - r));
    x1 ^= x0;
}

__device__ __forceinline__ uint32_t tf_bits_partitionable(uint32_t clo) {
    const uint32_t ks0 = 0u;
    const uint32_t ks1 = 42u;
    const uint32_t ks2 = 0x1BD11BDAu ^ 42u;   // ks0 ^ ks1 ^ 0x1BD11BDA

    uint32_t x0 = 0u;          // c_hi (=0) + ks0 (=0)
    uint32_t x1 = clo + ks1;

    tf_round(x0, x1, 13); tf_round(x0, x1, 15); tf_round(x0, x1, 26); tf_round(x0, x1, 6);
    x0 += ks1; x1 += ks2 + 1u;
    tf_round(x0, x1, 17); tf_round(x0, x1, 29); tf_round(x0, x1, 16); tf_round(x0, x1, 24);
    x0 += ks2; x1 += ks0 + 2u;
    tf_round(x0, x1, 13); tf_round(x0, x1, 15); tf_round(x0, x1, 26); tf_round(x0, x1, 6);
    x0 += ks0; x1 += ks1 + 3u;
    tf_round(x0, x1, 17); tf_round(x0, x1, 29); tf_round(x0, x1, 16); tf_round(x0, x1, 24);
    x0 += ks1; x1 += ks2 + 4u;
    tf_round(x0, x1, 13); tf_round(x0, x1, 15); tf_round(x0, x1, 26); tf_round(x0, x1, 6);
    x0 += ks2; x1 += ks0 + 5u;

    return x0 ^ x1;            // 32-bit partitionable combine
}

// JAX uniform(key, minval=tiny, maxval=1): bits -> [0,1) float, clamped to tiny.
__device__ __forceinline__ float bits_to_uniform(uint32_t bits) {
    float f = __uint_as_float(0x3F800000u | (bits >> 9)) - 1.0f;
    return fmaxf(f, 1.17549435e-38f);
}

// ---------------------------------------------------------------------------
// Kernel 0: logits[k] = log(pi[k] / sum(pi))
// (sum-order jitter shifts all logits by ~1 ulp; argmax-flip probability ~1e-7)
// ---------------------------------------------------------------------------
__global__ void logits_kernel(const float* __restrict__ pi) {
    __shared__ float ssum;
    if (threadIdx.x == 0) {
        float s = 0.0f;
        for (int k = 0; k < KMIX; k++) s += pi[k];
        ssum = s;
    }
    __syncthreads();
    int k = threadIdx.x;
    if (k < KMIX) g_logits[k] = logf(pi[k] / ssum);
}

// ---------------------------------------------------------------------------
// Kernel 1: categorical sampling, one thread per sample.
// z[n] = argmax_k ( -log(-log(u_{64n+k})) + logits[k] ), first-index ties.
// ---------------------------------------------------------------------------
__global__ __launch_bounds__(256) void sample_kernel() {
    __shared__ float s_logit[KMIX];
    if (threadIdx.x < KMIX) s_logit[threadIdx.x] = g_logits[threadIdx.x];
    __syncthreads();

    unsigned n = blockIdx.x * 256u + threadIdx.x;
    if (n >= NSAMP) return;

    uint32_t base = n * 64u;

    float best = -__int_as_float(0x7F800000);  // -inf
    int zi = 0;

    #pragma unroll 4
    for (int k = 0; k < KMIX; k++) {
        uint32_t bits = tf_bits_partitionable(base + (uint32_t)k);
        float u = bits_to_uniform(bits);
        float g = -logf(-logf(u));        // exact reference formula (libdevice logf)
        float v = g + s_logit[k];
        if (v > best) { best = v; zi = k; }
    }

    g_z[n] = zi;
}

// ---------------------------------------------------------------------------
// Kernel 2: y[n] = x[n]^T @ L[z[n]] + mu[z[n]]
// 16 threads per sample (one per output element). x staged in shared.
// Ls (64 KB) + means (4 KB) stay L1/L2-resident.
// ---------------------------------------------------------------------------
__global__ __launch_bounds__(256) void gather_matvec_kernel(
    const float* __restrict__ x,
    const float* __restrict__ means,
    const float* __restrict__ Ls,
    float* __restrict__ y)
{
    __shared__ float sx[256];
    int t = threadIdx.x;
    int gbase = blockIdx.x * 256;

    sx[t] = x[gbase + t];            // coalesced: 16 samples * 16 dims
    __syncthreads();

    int s = t >> 4;                  // local sample 0..15
    int e = t & 15;                  // output element 0..15
    int n = blockIdx.x * 16 + s;

    int z = g_z[n];
    const float* L = Ls + z * (DDIM * DDIM);

    float acc = __ldg(means + z * DDIM + e);
    #pragma unroll
    for (int d = 0; d < DDIM; d++)
        acc = fmaf(sx[(s << 4) + d], __ldg(L + d * DDIM + e), acc);

    y[n * DDIM + e] = acc;
}

// ---------------------------------------------------------------------------
extern "C" void kernel_launch(void* const* d_in, const int* in_sizes, int n_in,
                              void* d_out, int out_size) {
    const float* x     = (const float*)d_in[0];   // (N, D)
    const float* pi    = (const float*)d_in[1];   // (K,)
    const float* means = (const float*)d_in[2];   // (K, D)
    const float* Ls    = (const float*)d_in[3];   // (K, D, D)
    float* y           = (float*)d_out;           // (N, D)

    logits_kernel<<<1, 64>>>(pi);
    sample_kernel<<<(NSAMP + 255) / 256, 256>>>();
    gather_matvec_kernel<<<(NSAMP * DDIM) / 256, 256>>>(x, means, Ls, y);
}

// round 5
// speedup vs baseline: 1.1966x; 1.1966x over previous
#include <cuda_runtime.h>
#include <stdint.h>

// Problem constants
#define NSAMP 1000000
#define KMIX  64
#define DDIM  16

// Scratch (static __device__ — no allocation)
__device__ int   g_z[NSAMP];
__device__ float g_logits[KMIX];   // log(pi/sum)          (exact recheck path)
__device__ float g_w2[KMIX];       // ln2 * sum/pi_k       (fast screen path)

// ---------------------------------------------------------------------------
// Threefry-2x32, key = (0, 42), partitionable counter (0, i), combine o0^o1.
// ---------------------------------------------------------------------------
__device__ __forceinline__ void tf_round(uint32_t& x0, uint32_t& x1, int r) {
    x0 += x1;
    x1 = (x1 << r) | (x1 >> (32 - r));
    x1 ^= x0;
}

__device__ __forceinline__ uint32_t tf_bits_partitionable(uint32_t clo) {
    const uint32_t ks0 = 0u;
    const uint32_t ks1 = 42u;
    const uint32_t ks2 = 0x1BD11BDAu ^ 42u;

    uint32_t x0 = 0u;          // c_hi (=0) + ks0 (=0)
    uint32_t x1 = clo + ks1;

    tf_round(x0, x1, 13); tf_round(x0, x1, 15); tf_round(x0, x1, 26); tf_round(x0, x1, 6);
    x0 += ks1; x1 += ks2 + 1u;
    tf_round(x0, x1, 17); tf_round(x0, x1, 29); tf_round(x0, x1, 16); tf_round(x0, x1, 24);
    x0 += ks2; x1 += ks0 + 2u;
    tf_round(x0, x1, 13); tf_round(x0, x1, 15); tf_round(x0, x1, 26); tf_round(x0, x1, 6);
    x0 += ks0; x1 += ks1 + 3u;
    tf_round(x0, x1, 17); tf_round(x0, x1, 29); tf_round(x0, x1, 16); tf_round(x0, x1, 24);
    x0 += ks1; x1 += ks2 + 4u;
    tf_round(x0, x1, 13); tf_round(x0, x1, 15); tf_round(x0, x1, 26); tf_round(x0, x1, 6);
    x0 += ks2; x1 += ks0 + 5u;

    return x0 ^ x1;
}

// JAX uniform(key, minval=tiny, maxval=1): bits -> [0,1) float, clamped to tiny.
__device__ __forceinline__ float bits_to_uniform(uint32_t bits) {
    float f = __uint_as_float(0x3F800000u | (bits >> 9)) - 1.0f;
    return fmaxf(f, 1.17549435e-38f);
}

// ---------------------------------------------------------------------------
// Kernel 0: logits + screen weights. Serial sum order kept identical to the
// passing R4 run (bit-consistency).
// ---------------------------------------------------------------------------
__global__ void logits_kernel(const float* __restrict__ pi) {
    __shared__ float ssum;
    if (threadIdx.x == 0) {
        float s = 0.0f;
        for (int k = 0; k < KMIX; k++) s += pi[k];
        ssum = s;
    }
    __syncthreads();
    int k = threadIdx.x;
    if (k < KMIX) {
        g_logits[k] = logf(pi[k] / ssum);
        g_w2[k]     = 0.6931471805599453f * (ssum / pi[k]);   // ln2 * 1/p_k
    }
}

// ---------------------------------------------------------------------------
// Kernel 1: categorical sampling, one thread per sample.
// Screen: z = argmin_k (-log2(u_k)) * w2_k   (monotone-equiv to ref argmax).
// Exact recheck (full reference double-logf rescan) when top-2 margin is
// within 1e-3 (+1e-3 relative) — covers MUFU.LG2 error (<=6e-5 abs on m)
// with >=130x margin. Trigger rate ~2e-3/sample.
// ---------------------------------------------------------------------------
__global__ __launch_bounds__(256) void sample_kernel() {
    __shared__ float s_w2[KMIX];
    __shared__ float s_logit[KMIX];
    if (threadIdx.x < KMIX) {
        s_w2[threadIdx.x]    = g_w2[threadIdx.x];
        s_logit[threadIdx.x] = g_logits[threadIdx.x];
    }
    __syncthreads();

    unsigned n = blockIdx.x * 256u + threadIdx.x;
    if (n >= NSAMP) return;

    uint32_t base = n * 64u;

    const float INF = __int_as_float(0x7F800000);
    float m1 = INF, m2 = INF;
    int i1 = 0;

    #pragma unroll 8
    for (int k = 0; k < KMIX; k++) {
        uint32_t bits = tf_bits_partitionable(base + (uint32_t)k);
        float u  = bits_to_uniform(bits);
        float t2 = -__log2f(u);              // MUFU.LG2, t2 >= 0
        float m  = t2 * s_w2[k];
        if (m < m1) { m2 = m1; m1 = m; i1 = k; }
        else        { m2 = fminf(m2, m); }
    }

    int z = i1;
    if (m2 - m1 < 1e-3f + 1e-3f * m1) {
        // Exact reference-formula rescan (identical to the verified R4 path).
        float best = -INF;
        int zi = 0;
        for (int k = 0; k < KMIX; k++) {
            uint32_t bits = tf_bits_partitionable(base + (uint32_t)k);
            float u = bits_to_uniform(bits);
            float v = -logf(-logf(u)) + s_logit[k];
            if (v > best) { best = v; zi = k; }
        }
        z = zi;
    }

    g_z[n] = z;
}

// ---------------------------------------------------------------------------
// Kernel 2: y[n] = x[n]^T @ L[z[n]] + mu[z[n]]
// 4 threads per sample; each computes 4 outputs via float4 L loads.
// Per warp: 8 samples, fully coalesced float4 y stores (512B contiguous).
// ---------------------------------------------------------------------------
__global__ __launch_bounds__(256) void gather_matvec_kernel(
    const float* __restrict__ x,
    const float* __restrict__ means,
    const float* __restrict__ Ls,
    float* __restrict__ y)
{
    int t = threadIdx.x;
    int n = blockIdx.x * 64 + (t >> 2);      // sample index
    int q = t & 3;                           // output quarter (e = 4q..4q+3)

    const float4* x4 = (const float4*)x;
    float4 xa = __ldg(x4 + n * 4 + 0);
    float4 xb = __ldg(x4 + n * 4 + 1);
    float4 xc = __ldg(x4 + n * 4 + 2);
    float4 xd = __ldg(x4 + n * 4 + 3);
    float xr[16] = { xa.x, xa.y, xa.z, xa.w,
                     xb.x, xb.y, xb.z, xb.w,
                     xc.x, xc.y, xc.z, xc.w,
                     xd.x, xd.y, xd.z, xd.w };

    int z = g_z[n];
    const float4* L4  = (const float4*)Ls + z * 64 + q;   // row d -> L4[d*4]
    float4 acc = __ldg((const float4*)means + z * 4 + q);

    #pragma unroll
    for (int d = 0; d < DDIM; d++) {
        float4 lv = __ldg(L4 + d * 4);
        float xs = xr[d];
        acc.x = fmaf(xs, lv.x, acc.x);
        acc.y = fmaf(xs, lv.y, acc.y);
        acc.z = fmaf(xs, lv.z, acc.z);
        acc.w = fmaf(xs, lv.w, acc.w);
    }

    ((float4*)y)[n * 4 + q] = acc;
}

// ---------------------------------------------------------------------------
extern "C" void kernel_launch(void* const* d_in, const int* in_sizes, int n_in,
                              void* d_out, int out_size) {
    const float* x     = (const float*)d_in[0];   // (N, D)
    const float* pi    = (const float*)d_in[1];   // (K,)
    const float* means = (const float*)d_in[2];   // (K, D)
    const float* Ls    = (const float*)d_in[3];   // (K, D, D)
    float* y           = (float*)d_out;           // (N, D)

    logits_kernel<<<1, 64>>>(pi);
    sample_kernel<<<(NSAMP + 255) / 256, 256>>>();
    gather_matvec_kernel<<<NSAMP / 64, 256>>>(x, means, Ls, y);
}

// round 6
// speedup vs baseline: 1.3013x; 1.0876x over previous
#include <cuda_runtime.h>
#include <stdint.h>

// Problem constants
#define NSAMP 1000000
#define KMIX  64
#define DDIM  16

// ---------------------------------------------------------------------------
// Threefry-2x32, key = (0, 42), partitionable counter (0, i), combine o0^o1.
// Round 1 specialized: x0 starts at 0, so the first "x0 += x1" is x0 = x1.
// ---------------------------------------------------------------------------
__device__ __forceinline__ void tf_round(uint32_t& x0, uint32_t& x1, int r) {
    x0 += x1;
    x1 = (x1 << r) | (x1 >> (32 - r));
    x1 ^= x0;
}

__device__ __forceinline__ uint32_t tf_bits_partitionable(uint32_t clo) {
    const uint32_t ks0 = 0u;
    const uint32_t ks1 = 42u;
    const uint32_t ks2 = 0x1BD11BDAu ^ 42u;

    uint32_t x1 = clo + ks1;
    // round 1 specialized: x0 = 0 + x1
    uint32_t x0 = x1;
    x1 = ((x1 << 13) | (x1 >> 19)) ^ x0;

    tf_round(x0, x1, 15); tf_round(x0, x1, 26); tf_round(x0, x1, 6);
    x0 += ks1; x1 += ks2 + 1u;
    tf_round(x0, x1, 17); tf_round(x0, x1, 29); tf_round(x0, x1, 16); tf_round(x0, x1, 24);
    x0 += ks2; x1 += ks0 + 2u;
    tf_round(x0, x1, 13); tf_round(x0, x1, 15); tf_round(x0, x1, 26); tf_round(x0, x1, 6);
    x0 += ks0; x1 += ks1 + 3u;
    tf_round(x0, x1, 17); tf_round(x0, x1, 29); tf_round(x0, x1, 16); tf_round(x0, x1, 24);
    x0 += ks1; x1 += ks2 + 4u;
    tf_round(x0, x1, 13); tf_round(x0, x1, 15); tf_round(x0, x1, 26); tf_round(x0, x1, 6);
    x0 += ks2; x1 += ks0 + 5u;

    return x0 ^ x1;
}

// JAX uniform(key, minval=tiny, maxval=1): bits -> [0,1) float, clamped to tiny.
__device__ __forceinline__ float bits_to_uniform(uint32_t bits) {
    float f = __uint_as_float(0x3F800000u | (bits >> 9)) - 1.0f;
    return fmaxf(f, 1.17549435e-38f);
}

// ---------------------------------------------------------------------------
// Single fused kernel: per-block logits -> per-thread categorical sample
// -> per-thread matvec y[n] = x[n]^T L[z] + mu[z].
//
// Sampling screen: z = argmin_k (-log2(u_k)) * w2_k with w2_k = ln2/p_k
// (monotone-equivalent to reference argmax of Gumbel+logit). Exact
// reference-formula rescan (double accurate logf) when the top-2 margin is
// within 1e-3+1e-3*m1 — >=130x margin over worst-case MUFU.LG2 error.
// ---------------------------------------------------------------------------
__global__ __launch_bounds__(256) void fused_kernel(
    const float* __restrict__ pi,
    const float* __restrict__ x,
    const float* __restrict__ means,
    const float* __restrict__ Ls,
    float* __restrict__ y)
{
    __shared__ float s_w2[KMIX];
    __shared__ float s_logit[KMIX];
    __shared__ float s_sum;

    // Block-local logits (serial sum order identical to verified runs).
    if (threadIdx.x == 0) {
        float s = 0.0f;
        for (int k = 0; k < KMIX; k++) s += pi[k];
        s_sum = s;
    }
    __syncthreads();
    if (threadIdx.x < KMIX) {
        float ssum = s_sum;
        s_logit[threadIdx.x] = logf(pi[threadIdx.x] / ssum);
        s_w2[threadIdx.x]    = 0.6931471805599453f * (ssum / pi[threadIdx.x]);
    }
    __syncthreads();

    unsigned n = blockIdx.x * 256u + threadIdx.x;
    if (n >= NSAMP) return;

    uint32_t base = n * 64u;

    // ---- categorical sample ----
    const float INF = __int_as_float(0x7F800000);
    float m1 = INF, m2 = INF;
    int i1 = 0;

    #pragma unroll 8
    for (int k = 0; k < KMIX; k++) {
        uint32_t bits = tf_bits_partitionable(base + (uint32_t)k);
        float u  = bits_to_uniform(bits);
        float t2 = -__log2f(u);              // MUFU.LG2, t2 >= 0
        float m  = t2 * s_w2[k];
        if (m < m1) { m2 = m1; m1 = m; i1 = k; }
        else        { m2 = fminf(m2, m); }
    }

    int z = i1;
    if (m2 - m1 < 1e-3f + 1e-3f * m1) {
        // Exact reference-formula rescan (identical to verified path).
        float best = -INF;
        int zi = 0;
        for (int k = 0; k < KMIX; k++) {
            uint32_t bits = tf_bits_partitionable(base + (uint32_t)k);
            float u = bits_to_uniform(bits);
            float v = -logf(-logf(u)) + s_logit[k];
            if (v > best) { best = v; zi = k; }
        }
        z = zi;
    }

    // ---- matvec: y[n] = x[n]^T @ L[z] + mu[z] ----
    const float4* x4 = (const float4*)x + n * 4;
    float4 xa = __ldg(x4 + 0);
    float4 xb = __ldg(x4 + 1);
    float4 xc = __ldg(x4 + 2);
    float4 xd = __ldg(x4 + 3);
    float xr[16] = { xa.x, xa.y, xa.z, xa.w,
                     xb.x, xb.y, xb.z, xb.w,
                     xc.x, xc.y, xc.z, xc.w,
                     xd.x, xd.y, xd.z, xd.w };

    const float4* L4 = (const float4*)Ls + z * 64;      // row d -> L4[d*4 + q]
    const float4* m4 = (const float4*)means + z * 4;

    float4 acc[4];
    #pragma unroll
    for (int q = 0; q < 4; q++) acc[q] = __ldg(m4 + q);

    #pragma unroll
    for (int d = 0; d < DDIM; d++) {
        float xs = xr[d];
        #pragma unroll
        for (int q = 0; q < 4; q++) {
            float4 lv = __ldg(L4 + d * 4 + q);
            acc[q].x = fmaf(xs, lv.x, acc[q].x);
            acc[q].y = fmaf(xs, lv.y, acc[q].y);
            acc[q].z = fmaf(xs, lv.z, acc[q].z);
            acc[q].w = fmaf(xs, lv.w, acc[q].w);
        }
    }

    float4* y4 = (float4*)y + n * 4;
    #pragma unroll
    for (int q = 0; q < 4; q++) y4[q] = acc[q];
}

// ---------------------------------------------------------------------------
extern "C" void kernel_launch(void* const* d_in, const int* in_sizes, int n_in,
                              void* d_out, int out_size) {
    const float* x     = (const float*)d_in[0];   // (N, D)
    const float* pi    = (const float*)d_in[1];   // (K,)
    const float* means = (const float*)d_in[2];   // (K, D)
    const float* Ls    = (const float*)d_in[3];   // (K, D, D)
    float* y           = (float*)d_out;           // (N, D)

    fused_kernel<<<(NSAMP + 255) / 256, 256>>>(pi, x, means, Ls, y);
}